// round 17
// baseline (speedup 1.0000x reference)
#include <cuda_runtime.h>

// Gumbel-Sinkhorn, multiplicative form — dual-resident E (rows AND columns
// in registers), 256 threads per matrix, 1 CTA/SM.
//
//   E = exp((gamma + noise) * 5)            (once)
//   repeat niters: r_i = 1/sum_j E_ij c_j ;  c_j = 1/sum_i E_ij r_i
//   out_ij = E_ij * r_i * c_j
//
// Thread t = (r2 = t>>1, h = t&1) owns in packed f32x2 registers:
//   rowE: E[r2][64h .. 64h+63]   (32 ull)  — row-pass operand
//   colE: E[64h .. 64h+63][r2]   (32 ull, packed along rows) — col-pass operand
// Each pass: 16 broadcast LDS.128 of the opposing vector + 32 FFMA2;
// halves combined with ONE shfl_xor(1) (partner lane owns the other half).
// No per-iteration E traffic, no part buffer, no reduce stage — per-iter
// smem drops from ~1456 wf (R10) to ~258, issue from ~560 to ~236/SMSP.
// 2 CTA barriers per iteration (r and c visibility).

#define NN 128
#define STRIDE 132           // Es row stride (floats)
#define TEMP_INV 5.0f
#define NT 256

typedef unsigned long long ull;

__device__ __forceinline__ ull pack2(float lo, float hi) {
    ull r; asm("mov.b64 %0, {%1, %2};" : "=l"(r) : "f"(lo), "f"(hi)); return r;
}
__device__ __forceinline__ void fma2(ull& d, ull a, ull b) {
    asm("fma.rn.f32x2 %0, %1, %2, %0;" : "+l"(d) : "l"(a), "l"(b));
}
__device__ __forceinline__ ull add2(ull a, ull b) {
    ull r; asm("add.rn.f32x2 %0, %1, %2;" : "=l"(r) : "l"(a), "l"(b)); return r;
}
__device__ __forceinline__ void unpack2(ull v, float& lo, float& hi) {
    asm("mov.b64 {%0, %1}, %2;" : "=f"(lo), "=f"(hi) : "l"(v));
}
__device__ __forceinline__ float frcp(float x) {
    float r; asm("rcp.approx.f32 %0, %1;" : "=f"(r) : "f"(x)); return r;
}

__global__ __launch_bounds__(NT, 1) void sinkhorn_kernel(
    const float* __restrict__ gamma,
    const float* __restrict__ noise,
    const int*   __restrict__ niters_p,
    float*       __restrict__ out)
{
    extern __shared__ float smem[];
    float* Es  = smem;                    // NN * STRIDE (prologue/epilogue only)
    float* r_s = smem + NN * STRIDE;      // NN
    float* c_s = r_s + NN;                // NN

    const int tid = threadIdx.x;
    const int r2  = tid >> 1;             // row / column index owned
    const int h   = tid & 1;              // which 64-element half
    const long long base = (long long)blockIdx.x * (NN * NN);
    const int niters = *niters_p;

    // ---- Prologue: E = exp((gamma + noise) * 5) into smem, coalesced ----
    const float4* g4 = reinterpret_cast<const float4*>(gamma);
    const float4* n4 = reinterpret_cast<const float4*>(noise + base);
    #pragma unroll
    for (int k = 0; k < 16; ++k) {
        int v  = k * NT + tid;            // float4 index 0..4095
        int i  = v >> 5;                  // row
        int j4 = (v & 31) * 4;            // col
        float4 g = g4[v];
        float4 u = n4[v];
        float4 e;
        e.x = __expf((g.x + u.x) * TEMP_INV);
        e.y = __expf((g.y + u.y) * TEMP_INV);
        e.z = __expf((g.z + u.z) * TEMP_INV);
        e.w = __expf((g.w + u.w) * TEMP_INV);
        *reinterpret_cast<float4*>(&Es[i * STRIDE + j4]) = e;
    }
    if (tid < NN) c_s[tid] = 1.0f;
    __syncthreads();

    // ---- Fill register copies (one-time) ----
    ull rowE[32];                          // E[r2][64h + 2p], pairs along columns
    #pragma unroll
    for (int m = 0; m < 16; ++m) {
        ulonglong2 e = *reinterpret_cast<const ulonglong2*>(
            &Es[r2 * STRIDE + 64 * h + 4 * m]);
        rowE[2 * m + 0] = e.x;
        rowE[2 * m + 1] = e.y;
    }
    ull colE[32];                          // (E[64h+2p][r2], E[64h+2p+1][r2])
    #pragma unroll
    for (int p = 0; p < 32; ++p) {
        float lo = Es[(64 * h + 2 * p + 0) * STRIDE + r2];
        float hi = Es[(64 * h + 2 * p + 1) * STRIDE + r2];
        colE[p] = pack2(lo, hi);
    }

    float r = 1.0f;

    // ---- Sinkhorn iterations (lockstep: 2 barriers each) ----
    for (int it = 0; it < niters; ++it) {
        // Row pass: S_{r2} over cols [64h, 64h+64); c pairs loaded as ull2.
        ull a0 = 0, a1 = 0, a2 = 0, a3 = 0;
        const float* cb = &c_s[64 * h];
        #pragma unroll
        for (int q = 0; q < 8; ++q) {
            ulonglong2 c0 = *reinterpret_cast<const ulonglong2*>(&cb[8 * q]);
            ulonglong2 c1 = *reinterpret_cast<const ulonglong2*>(&cb[8 * q + 4]);
            fma2(a0, rowE[4 * q + 0], c0.x);
            fma2(a1, rowE[4 * q + 1], c0.y);
            fma2(a2, rowE[4 * q + 2], c1.x);
            fma2(a3, rowE[4 * q + 3], c1.y);
        }
        ull as = add2(add2(a0, a1), add2(a2, a3));
        float slo, shi; unpack2(as, slo, shi);
        float S = slo + shi;
        S += __shfl_xor_sync(0xffffffffu, S, 1);   // other half of this row
        r = frcp(S);
        if (h == 0) r_s[r2] = r;                   // 16 consecutive banks / warp
        __syncthreads();                           // all r visible

        // Col pass: T_{r2} over rows [64h, 64h+64); consecutive r pairs
        // align exactly with the row-packed colE — no splats needed.
        ull b0 = 0, b1 = 0, b2 = 0, b3 = 0;
        const float* rb = &r_s[64 * h];
        #pragma unroll
        for (int q = 0; q < 8; ++q) {
            ulonglong2 r0 = *reinterpret_cast<const ulonglong2*>(&rb[8 * q]);
            ulonglong2 r1 = *reinterpret_cast<const ulonglong2*>(&rb[8 * q + 4]);
            fma2(b0, colE[4 * q + 0], r0.x);
            fma2(b1, colE[4 * q + 1], r0.y);
            fma2(b2, colE[4 * q + 2], r1.x);
            fma2(b3, colE[4 * q + 3], r1.y);
        }
        ull bs = add2(add2(b0, b1), add2(b2, b3));
        float tlo, thi; unpack2(bs, tlo, thi);
        float T = tlo + thi;
        T += __shfl_xor_sync(0xffffffffu, T, 1);   // other half of this column
        if (h == 0) c_s[r2] = frcp(T);
        __syncthreads();                           // all c visible
    }

    // ---- Epilogue: out = E * r * c from smem Es (coalesced, R10 style) ----
    float4* o4 = reinterpret_cast<float4*>(out + base);
    #pragma unroll
    for (int k = 0; k < 16; ++k) {
        int v  = k * NT + tid;
        int i  = v >> 5;
        int j4 = (v & 31) * 4;
        float ri = r_s[i];
        float4 e = *reinterpret_cast<const float4*>(&Es[i * STRIDE + j4]);
        float4 o;
        o.x = e.x * ri * c_s[j4 + 0];
        o.y = e.y * ri * c_s[j4 + 1];
        o.z = e.z * ri * c_s[j4 + 2];
        o.w = e.w * ri * c_s[j4 + 3];
        o4[v] = o;
    }
}

extern "C" void kernel_launch(void* const* d_in, const int* in_sizes, int n_in,
                              void* d_out, int out_size)
{
    // Identify inputs by element count:
    //   gamma: 128*128, noise: B*128*128 (largest), niters: 1
    int gi = -1, ni = -1, si = -1;
    long long best = -1;
    for (int k = 0; k < n_in; ++k) {
        if (in_sizes[k] == 1) { si = k; }
        else if (in_sizes[k] == NN * NN && gi < 0) { gi = k; }
        if ((long long)in_sizes[k] > best) { best = in_sizes[k]; ni = k; }
    }
    if (ni == gi) {
        for (int k = 0; k < n_in; ++k)
            if (k != gi && in_sizes[k] == NN * NN) { ni = k; break; }
    }

    const float* gamma = (const float*)d_in[gi];
    const float* noise = (const float*)d_in[ni];
    const int*   nit   = (const int*)d_in[si];
    float* out = (float*)d_out;

    int B = in_sizes[ni] / (NN * NN);

    const int smem_bytes = (NN * STRIDE + 2 * NN) * (int)sizeof(float);
    static bool attr_set = false;
    if (!attr_set) {
        cudaFuncSetAttribute(sinkhorn_kernel,
                             cudaFuncAttributeMaxDynamicSharedMemorySize,
                             smem_bytes);
        attr_set = true;
    }

    sinkhorn_kernel<<<B, NT, smem_bytes>>>(gamma, noise, nit, out);
}